// round 16
// baseline (speedup 1.0000x reference)
#include <cuda_runtime.h>
#include <cuda_fp16.h>
#include <cstdint>

// ---------------------------------------------------------------------------
// B=2, N=2048, KD=VD=ID=1024, H=16, HD=64
// ---------------------------------------------------------------------------
#define MROWS 4096
#define DIM   1024
#define QKN   2048
#define HEADS 16
#define HDIM  64
#define SEQ   2048
// folded into q at lnqk: SCALE * log2(e) = 1.44269504 / 32
#define K2E 0.0450842200f

// ---------------------------------------------------------------------------
// Device scratch
// ---------------------------------------------------------------------------
__device__ __half g_kn[MROWS * DIM];
__device__ __half g_vn[MROWS * DIM];
__device__ __half g_qkh[MROWS * QKN];
__device__ __half g_qh[MROWS * DIM];
__device__ __half g_kh[MROWS * DIM];
__device__ __half g_vh[MROWS * DIM];
__device__ __half g_ao[MROWS * DIM];

// ---------------------------------------------------------------------------
// PTX helpers
// ---------------------------------------------------------------------------
__device__ __forceinline__ uint32_t smem_u32(const void* p) {
    return (uint32_t)__cvta_generic_to_shared(p);
}
#define CP16(dst, src) \
    asm volatile("cp.async.cg.shared.global [%0], [%1], 16;" :: "r"(dst), "l"(src))
#define CP_COMMIT() asm volatile("cp.async.commit_group;" ::: "memory")
#define CP_WAIT(n)  asm volatile("cp.async.wait_group %0;" :: "n"(n) : "memory")

__device__ __forceinline__ void ldm_x4(uint32_t* r, uint32_t a) {
    asm volatile("ldmatrix.sync.aligned.m8n8.x4.shared.b16 {%0,%1,%2,%3}, [%4];"
        : "=r"(r[0]), "=r"(r[1]), "=r"(r[2]), "=r"(r[3]) : "r"(a));
}
__device__ __forceinline__ void ldm_x4t(uint32_t* r, uint32_t a) {
    asm volatile("ldmatrix.sync.aligned.m8n8.x4.trans.shared.b16 {%0,%1,%2,%3}, [%4];"
        : "=r"(r[0]), "=r"(r[1]), "=r"(r[2]), "=r"(r[3]) : "r"(a));
}
__device__ __forceinline__ void mma16816(float* c, const uint32_t* a,
                                         uint32_t b0, uint32_t b1) {
    asm volatile(
        "mma.sync.aligned.m16n8k16.row.col.f32.f16.f16.f32 "
        "{%0,%1,%2,%3}, {%4,%5,%6,%7}, {%8,%9}, {%0,%1,%2,%3};"
        : "+f"(c[0]), "+f"(c[1]), "+f"(c[2]), "+f"(c[3])
        : "r"(a[0]), "r"(a[1]), "r"(a[2]), "r"(a[3]), "r"(b0), "r"(b1));
}
// fp16-accumulator variant: C is 2 packed half2 regs. (flash QK only)
__device__ __forceinline__ void mma16816h(uint32_t* c, const uint32_t* a,
                                          uint32_t b0, uint32_t b1) {
    asm volatile(
        "mma.sync.aligned.m16n8k16.row.col.f16.f16.f16.f16 "
        "{%0,%1}, {%2,%3,%4,%5}, {%6,%7}, {%0,%1};"
        : "+r"(c[0]), "+r"(c[1])
        : "r"(a[0]), "r"(a[1]), "r"(a[2]), "r"(a[3]), "r"(b0), "r"(b1));
}
__device__ __forceinline__ uint32_t pack_half2(float lo, float hi) {
    uint32_t u;
    asm("cvt.rn.f16x2.f32 %0, %1, %2;" : "=r"(u) : "f"(hi), "f"(lo));
    return u;
}
__device__ __forceinline__ __half2 u2h(uint32_t u) {
    return *reinterpret_cast<__half2*>(&u);
}
__device__ __forceinline__ uint32_t h2u(__half2 h) {
    return *reinterpret_cast<uint32_t*>(&h);
}

// Packed softmax numerator: 2^(s') * 2^-6, fully in half2.
__device__ __forceinline__ __half2 pexp2h(uint32_t sbits) {
    const __half2 s2 = u2h(sbits);
    const __half2 mg = u2h(0x66046604u);           // 1540.0 x2
    const __half2 t2 = __hadd2(s2, mg);            // round-to-int (RN)
    const __half2 f2 = __hsub2(t2, mg);            // k (integer)
    const __half2 r2 = __hsub2(s2, f2);            // frac in [-0.5, 0.5]
    __half2 p = __hfma2(u2h(0x20EC20ECu), r2, u2h(0x2B1A2B1Au));
    p = __hfma2(p, r2, u2h(0x33B033B0u));
    p = __hfma2(p, r2, u2h(0x398C398Cu));
    p = __hfma2(p, r2, u2h(0x3C003C00u));
    const uint32_t sc = ((h2u(t2) << 10) & 0x1C001C00u) + 0x14001400u;
    return __hmul2(p, u2h(sc));
}

// ---------------------------------------------------------------------------
// Combined input LayerNorm: blockIdx.y selects (keys->kn) or (values->vn).
// One warp per row. g/b loads hoisted ABOVE the reduce: 24 outstanding LDGs
// per warp hide the gamma/beta L2 latency under the shfl chain.
// ---------------------------------------------------------------------------
__global__ __launch_bounds__(256) void ln2_h(
    const float* __restrict__ x0, const float* __restrict__ g0,
    const float* __restrict__ b0, __half* __restrict__ y0,
    const float* __restrict__ x1, const float* __restrict__ g1,
    const float* __restrict__ b1, __half* __restrict__ y1)
{
    const float* x = blockIdx.y ? x1 : x0;
    const float* g = blockIdx.y ? g1 : g0;
    const float* b = blockIdx.y ? b1 : b0;
    __half*      y = blockIdx.y ? y1 : y0;

    const int lane = threadIdx.x & 31;
    const size_t row = (size_t)blockIdx.x * 8 + (threadIdx.x >> 5);
    const float* xr = x + row * (size_t)DIM;

    float4 v[8], gv[8], bv[8];
    float s = 0.f, ss = 0.f;
    #pragma unroll
    for (int i = 0; i < 8; i++) {
        const int c4 = i * 32 + lane;
        v[i]  = *(const float4*)(xr + c4 * 4);
        gv[i] = *(const float4*)(g + c4 * 4);
        bv[i] = *(const float4*)(b + c4 * 4);
    }
    #pragma unroll
    for (int i = 0; i < 8; i++) {
        s  += v[i].x + v[i].y + v[i].z + v[i].w;
        ss += v[i].x*v[i].x + v[i].y*v[i].y + v[i].z*v[i].z + v[i].w*v[i].w;
    }
    #pragma unroll
    for (int m = 16; m; m >>= 1) {
        s  += __shfl_xor_sync(0xffffffffu, s,  m);
        ss += __shfl_xor_sync(0xffffffffu, ss, m);
    }
    const float mu   = s * (1.0f / 1024.0f);
    const float rstd = rsqrtf(ss * (1.0f / 1024.0f) - mu * mu + 1e-5f);

    #pragma unroll
    for (int i = 0; i < 8; i++) {
        const int c4 = i * 32 + lane;
        uint2 o;
        o.x = pack_half2((v[i].x - mu) * rstd * gv[i].x + bv[i].x,
                         (v[i].y - mu) * rstd * gv[i].y + bv[i].y);
        o.y = pack_half2((v[i].z - mu) * rstd * gv[i].z + bv[i].z,
                         (v[i].w - mu) * rstd * gv[i].w + bv[i].w);
        *(uint2*)(y + row * (size_t)DIM + c4 * 4) = o;
    }
}

// ---------------------------------------------------------------------------
// q/k LayerNorm, split: blockIdx.y = 0 -> q half (pre-scaled by K2E),
// 1 -> k half. One warp per row-half; g/b loads hoisted above the reduce.
// ---------------------------------------------------------------------------
__global__ __launch_bounds__(256) void lnqk2_h(
    const __half* __restrict__ qk,
    const float* __restrict__ qg, const float* __restrict__ qb,
    const float* __restrict__ kg, const float* __restrict__ kb,
    __half* __restrict__ qh, __half* __restrict__ kh)
{
    const int isK = blockIdx.y;
    const float* g = isK ? kg : qg;
    const float* b = isK ? kb : qb;
    __half*      y = isK ? kh : qh;
    const float post = isK ? 1.0f : K2E;

    const int lane = threadIdx.x & 31;
    const size_t row = (size_t)blockIdx.x * 8 + (threadIdx.x >> 5);
    const __half* xr = qk + row * (size_t)QKN + isK * DIM;

    uint2 u[8];
    float4 gv[8], bv[8];
    float s = 0.f, ss = 0.f;
    #pragma unroll
    for (int i = 0; i < 8; i++) {
        const int c4 = i * 32 + lane;
        u[i]  = *(const uint2*)(xr + c4 * 4);
        gv[i] = *(const float4*)(g + c4 * 4);
        bv[i] = *(const float4*)(b + c4 * 4);
    }
    #pragma unroll
    for (int i = 0; i < 8; i++) {
        const __half2* h = (const __half2*)&u[i];
        #pragma unroll
        for (int p = 0; p < 2; p++) {
            const float2 f = __half22float2(h[p]);
            s += f.x + f.y;  ss += f.x*f.x + f.y*f.y;
        }
    }
    #pragma unroll
    for (int m = 16; m; m >>= 1) {
        s  += __shfl_xor_sync(0xffffffffu, s,  m);
        ss += __shfl_xor_sync(0xffffffffu, ss, m);
    }
    const float mu = s * (1.0f / 1024.0f);
    const float r  = rsqrtf(ss * (1.0f / 1024.0f) - mu * mu + 1e-5f);

    #pragma unroll
    for (int i = 0; i < 8; i++) {
        const int c4 = i * 32 + lane;
        const __half2* h = (const __half2*)&u[i];
        const float2 f0 = __half22float2(h[0]), f1 = __half22float2(h[1]);
        uint2 o;
        o.x = pack_half2(((f0.x - mu) * r * gv[i].x + bv[i].x) * post,
                         ((f0.y - mu) * r * gv[i].y + bv[i].y) * post);
        o.y = pack_half2(((f1.x - mu) * r * gv[i].z + bv[i].z) * post,
                         ((f1.y - mu) * r * gv[i].w + bv[i].w) * post);
        *(uint2*)(y + row * (size_t)DIM + c4 * 4) = o;
    }
}

// ---------------------------------------------------------------------------
// fp16 GEMM, direct-B (R11/R13/R15, unchanged):
// C[M,N] = A[M,K] @ B[K,N] (+bias).
// A: fp16 [M][K], cp.async 3-stage, ldmatrix. B: fp32 [K][N] raw weights,
// LDG+cvt+STS 2-stage, ldmatrix.trans fragments.
// CTA 128x128, 8 warps (2x4), warp tile 64x32, K-chunk 64, 2 CTAs/SM.
// ---------------------------------------------------------------------------
#define GST  72
#define BST  136
#define ASTG (128 * GST)
#define BSTG (64 * BST)
#define GEMM_SMEM ((3 * ASTG + 2 * BSTG) * 2)   // 90112 B

template <bool HALF_OUT>
__global__ __launch_bounds__(256, 2) void gemm_mma(
    const __half* __restrict__ A, const float* __restrict__ Bf,
    const float* __restrict__ bias, void* __restrict__ Cv,
    int K, int ldB, int ldC)
{
    extern __shared__ __align__(16) __half sm[];
    const uint32_t sb  = smem_u32(sm);
    const uint32_t bb0 = sb + 3 * ASTG * 2;

    const int tid  = threadIdx.x;
    const int wid  = tid >> 5, lane = tid & 31;
    const int g = lane >> 2, tg = lane & 3;
    const int m0 = (wid >> 2) * 64, n0 = (wid & 3) * 32;
    const int lr = (lane & 7) + ((lane >> 3) & 1) * 8;
    const int lc = (lane >> 4) * 8;

    const __half* Ag = A  + (size_t)(blockIdx.y * 128) * K;
    const float*  Bg = Bf + blockIdx.x * 128;

    const int lrow = tid >> 3, lcol = (tid & 7) * 8;   // A cp.async mapping
    const int brow = tid >> 5, bcol = (tid & 31) * 4;  // B LDG/STS mapping

    auto load_a = [&](int s, int kc) {
        const uint32_t ab = sb + s * ASTG * 2;
        #pragma unroll
        for (int i = 0; i < 4; i++) {
            const int row = lrow + i * 32;
            CP16(ab + (row * GST + lcol) * 2, Ag + (size_t)row * K + kc * 64 + lcol);
        }
        CP_COMMIT();
    };
    auto ldg_b = [&](float4* bv, int kc, int half) {
        const float* Bk = Bg + (size_t)(kc * 64) * ldB;
        #pragma unroll
        for (int i = 0; i < 4; i++) {
            const int row = brow + (half * 4 + i) * 8;
            bv[i] = *(const float4*)(Bk + (size_t)row * ldB + bcol);
        }
    };
    auto sts_b = [&](const float4* bv, uint32_t bbuf, int half) {
        #pragma unroll
        for (int i = 0; i < 4; i++) {
            const int row = brow + (half * 4 + i) * 8;
            const uint32_t u0 = pack_half2(bv[i].x, bv[i].y);
            const uint32_t u1 = pack_half2(bv[i].z, bv[i].w);
            asm volatile("st.shared.v2.b32 [%0], {%1,%2};"
                :: "r"(bbuf + (row * BST + bcol) * 2), "r"(u0), "r"(u1));
        }
    };

    float acc[4][4][4];
    #pragma unroll
    for (int i = 0; i < 4; i++)
        #pragma unroll
        for (int j = 0; j < 4; j++)
            #pragma unroll
            for (int q = 0; q < 4; q++) acc[i][j][q] = 0.f;

    const int nk = K >> 6;
    load_a(0, 0);
    load_a(1, 1);
    {   // B prologue: fill stage 0
        float4 bv[4];
        ldg_b(bv, 0, 0); sts_b(bv, bb0, 0);
        ldg_b(bv, 0, 1); sts_b(bv, bb0, 1);
    }

    for (int kc = 0; kc < nk; kc++) {
        if (kc + 1 < nk) CP_WAIT(1); else CP_WAIT(0);
        __syncthreads();
        if (kc + 2 < nk) load_a((kc + 2) % 3, kc + 2);

        const uint32_t ab   = sb + (kc % 3) * ASTG * 2;
        const uint32_t bbuf = bb0 + (kc & 1) * BSTG * 2;
        const uint32_t bnxt = bb0 + ((kc + 1) & 1) * BSTG * 2;
        const bool more = (kc + 1 < nk);

        float4 bv[4];
        if (more) ldg_b(bv, kc + 1, 0);

        #pragma unroll
        for (int ks = 0; ks < 4; ks++) {
            if (ks == 2 && more) {
                sts_b(bv, bnxt, 0);
                ldg_b(bv, kc + 1, 1);
            }
            uint32_t a[4][4];
            #pragma unroll
            for (int mi = 0; mi < 4; mi++)
                ldm_x4(a[mi], ab + ((m0 + mi * 16 + lr) * GST + ks * 16 + lc) * 2);
            #pragma unroll
            for (int np = 0; np < 2; np++) {
                uint32_t bf[4];
                ldm_x4t(bf, bbuf + ((ks * 16 + lr) * BST + n0 + np * 16 + lc) * 2);
                #pragma unroll
                for (int ni2 = 0; ni2 < 2; ni2++) {
                    #pragma unroll
                    for (int mi = 0; mi < 4; mi++)
                        mma16816(acc[mi][np * 2 + ni2], a[mi],
                                 bf[ni2 * 2], bf[ni2 * 2 + 1]);
                }
            }
        }
        if (more) sts_b(bv, bnxt, 1);
        __syncthreads();
    }

    const int crow = blockIdx.y * 128 + m0;
    const int ccol = blockIdx.x * 128 + n0;
    #pragma unroll
    for (int mi = 0; mi < 4; mi++) {
        #pragma unroll
        for (int ni = 0; ni < 4; ni++) {
            const int r = crow + mi * 16 + g;
            const int c = ccol + ni * 8 + 2 * tg;
            float2 v0 = make_float2(acc[mi][ni][0], acc[mi][ni][1]);
            float2 v1 = make_float2(acc[mi][ni][2], acc[mi][ni][3]);
            if (bias) {
                const float2 bb2 = *(const float2*)(bias + c);
                v0.x += bb2.x; v0.y += bb2.y; v1.x += bb2.x; v1.y += bb2.y;
            }
            if (HALF_OUT) {
                __half* C = (__half*)Cv;
                *(uint32_t*)&C[(size_t)r * ldC + c]       = pack_half2(v0.x, v0.y);
                *(uint32_t*)&C[(size_t)(r + 8) * ldC + c] = pack_half2(v1.x, v1.y);
            } else {
                float* C = (float*)Cv;
                *(float2*)&C[(size_t)r * ldC + c]       = v0;
                *(float2*)&C[(size_t)(r + 8) * ldC + c] = v1;
            }
        }
    }
}

// ---------------------------------------------------------------------------
// Flash attention (R10-R15, unchanged): fp16-accum QK, packed half2 softmax,
// fp32-accum PV. CTA = 128 q-rows, 8 warps x 16, 2 CTAs/SM.
// ---------------------------------------------------------------------------
#define FQ_ROWS 128
#define FKV_OFF (FQ_ROWS * GST)
#define FSTAGE  (128 * GST)
#define FLASH_SMEM ((FQ_ROWS * GST + 2 * FSTAGE) * 2)   // 55296 B

__global__ __launch_bounds__(256, 2) void flash_mma(
    const __half* __restrict__ Q, const __half* __restrict__ Kg,
    const __half* __restrict__ Vg, __half* __restrict__ Og)
{
    extern __shared__ __align__(16) __half sm[];
    const uint32_t sb = smem_u32(sm);

    const int tid  = threadIdx.x;
    const int warp = tid >> 5, lane = tid & 31;
    const int g = lane >> 2, tg = lane & 3;
    const int m0 = warp * 16;
    const int lr = (lane & 7) + ((lane >> 3) & 1) * 8;
    const int lc = (lane >> 4) * 8;

    const size_t q0 = (size_t)blockIdx.x * FQ_ROWS;
    const int hc = blockIdx.y * HDIM;

    const int lrow = tid >> 3, lcol = (tid & 7) * 8;

    {
        const __half* qg = Q + q0 * DIM + hc;
        #pragma unroll
        for (int i = 0; i < 4; i++) {
            const int row = lrow + i * 32;
            CP16(sb + (row * GST + lcol) * 2, qg + (size_t)row * DIM + lcol);
        }
    }
    auto load_kv = [&](int s, int kt) {
        const __half* kg = Kg + (size_t)(kt * 64) * DIM + hc;
        const __half* vg = Vg + (size_t)(kt * 64) * DIM + hc;
        const uint32_t kb = sb + (FKV_OFF + s * FSTAGE) * 2;
        const uint32_t vb = kb + 64 * GST * 2;
        #pragma unroll
        for (int i = 0; i < 2; i++) {
            const int row = lrow + i * 32;
            CP16(kb + (row * GST + lcol) * 2, kg + (size_t)row * DIM + lcol);
            CP16(vb + (row * GST + lcol) * 2, vg + (size_t)row * DIM + lcol);
        }
        CP_COMMIT();
    };
    load_kv(0, 0);

    uint32_t qf[4][4];
    float o[8][4];
    #pragma unroll
    for (int j = 0; j < 8; j++)
        #pragma unroll
        for (int q = 0; q < 4; q++) o[j][q] = 0.f;
    float l0 = 0.f, l1 = 0.f;

    for (int kt = 0; kt < SEQ / 64; kt++) {
        if (kt + 1 < SEQ / 64) { load_kv((kt + 1) & 1, kt + 1); CP_WAIT(1); }
        else                   { CP_WAIT(0); }
        __syncthreads();

        if (kt == 0) {
            #pragma unroll
            for (int s = 0; s < 4; s++)
                ldm_x4(qf[s], sb + ((m0 + lr) * GST + s * 16 + lc) * 2);
        }

        const uint32_t kb = sb + (FKV_OFF + (kt & 1) * FSTAGE) * 2;
        const uint32_t vb = kb + 64 * GST * 2;

        uint32_t sh[8][2];
        #pragma unroll
        for (int j = 0; j < 8; j++) { sh[j][0] = 0u; sh[j][1] = 0u; }
        #pragma unroll
        for (int ks = 0; ks < 4; ks++) {
            uint32_t bf[4][4];
            #pragma unroll
            for (int np = 0; np < 4; np++)
                ldm_x4(bf[np], kb + ((np * 16 + lr) * GST + ks * 16 + lc) * 2);
            #pragma unroll
            for (int j = 0; j < 8; j++)
                mma16816h(sh[j], qf[ks], bf[j >> 1][j & 1], bf[j >> 1][(j & 1) + 2]);
        }

        uint32_t pf[4][4];
        __half2 la = u2h(0u), lb = u2h(0u);
        #pragma unroll
        for (int j = 0; j < 8; j++) {
            const __half2 pa = pexp2h(sh[j][0]);
            const __half2 pb = pexp2h(sh[j][1]);
            la = __hadd2(la, pa);
            lb = __hadd2(lb, pb);
            pf[j >> 1][(j & 1) * 2]     = h2u(pa);
            pf[j >> 1][(j & 1) * 2 + 1] = h2u(pb);
        }
        l0 += __low2float(la) + __high2float(la);
        l1 += __low2float(lb) + __high2float(lb);

        #pragma unroll
        for (int ks = 0; ks < 4; ks++) {
            uint32_t vf[4][4];
            #pragma unroll
            for (int np = 0; np < 4; np++)
                ldm_x4t(vf[np], vb + ((ks * 16 + lr) * GST + np * 16 + lc) * 2);
            #pragma unroll
            for (int j = 0; j < 8; j++)
                mma16816(o[j], pf[ks],
                         vf[j >> 1][(j & 1) * 2], vf[j >> 1][(j & 1) * 2 + 1]);
        }
        __syncthreads();
    }

    l0 += __shfl_xor_sync(0xffffffffu, l0, 1);
    l0 += __shfl_xor_sync(0xffffffffu, l0, 2);
    l1 += __shfl_xor_sync(0xffffffffu, l1, 1);
    l1 += __shfl_xor_sync(0xffffffffu, l1, 2);
    const float inv0 = 1.0f / l0, inv1 = 1.0f / l1;

    const size_t row0 = q0 + m0 + g;
    #pragma unroll
    for (int j = 0; j < 8; j++) {
        const int c = hc + j * 8 + 2 * tg;
        *(uint32_t*)&Og[row0 * DIM + c]       = pack_half2(o[j][0] * inv0, o[j][1] * inv0);
        *(uint32_t*)&Og[(row0 + 8) * DIM + c] = pack_half2(o[j][2] * inv1, o[j][3] * inv1);
    }
}

// ---------------------------------------------------------------------------
// Launcher: R15 schedule, unchanged (combined input-LN; stream B = full
// v-GEMM then batch-1 chain; stream A = batch-0 chain waiting on eV).
// ---------------------------------------------------------------------------
extern "C" void kernel_launch(void* const* d_in, const int* in_sizes, int n_in,
                              void* d_out, int out_size)
{
    const float* keys    = (const float*)d_in[0];
    const float* values  = (const float*)d_in[1];
    const float* qk_g    = (const float*)d_in[2];
    const float* qk_b    = (const float*)d_in[3];
    const float* vn_g    = (const float*)d_in[4];
    const float* vn_b    = (const float*)d_in[5];
    const float* key_g   = (const float*)d_in[6];
    const float* key_b   = (const float*)d_in[7];
    const float* query_g = (const float*)d_in[8];
    const float* query_b = (const float*)d_in[9];
    const float* w_qk    = (const float*)d_in[10];
    const float* w_v     = (const float*)d_in[11];
    const float* w_out   = (const float*)d_in[12];
    const float* b_out   = (const float*)d_in[13];
    float* out = (float*)d_out;

    __half *kn, *vn, *qkh, *qh, *kh, *vh, *ao;
    cudaGetSymbolAddress((void**)&kn,  g_kn);
    cudaGetSymbolAddress((void**)&vn,  g_vn);
    cudaGetSymbolAddress((void**)&qkh, g_qkh);
    cudaGetSymbolAddress((void**)&qh,  g_qh);
    cudaGetSymbolAddress((void**)&kh,  g_kh);
    cudaGetSymbolAddress((void**)&vh,  g_vh);
    cudaGetSymbolAddress((void**)&ao,  g_ao);

    static cudaStream_t sB = nullptr;
    static cudaEvent_t  eKN = nullptr, eV = nullptr, eB1 = nullptr;
    if (!sB) {
        cudaStreamCreateWithFlags(&sB, cudaStreamNonBlocking);
        cudaEventCreateWithFlags(&eKN, cudaEventDisableTiming);
        cudaEventCreateWithFlags(&eV,  cudaEventDisableTiming);
        cudaEventCreateWithFlags(&eB1, cudaEventDisableTiming);
        cudaFuncSetAttribute(gemm_mma<false>,
            cudaFuncAttributeMaxDynamicSharedMemorySize, GEMM_SMEM);
        cudaFuncSetAttribute(gemm_mma<true>,
            cudaFuncAttributeMaxDynamicSharedMemorySize, GEMM_SMEM);
        cudaFuncSetAttribute(flash_mma,
            cudaFuncAttributeMaxDynamicSharedMemorySize, FLASH_SMEM);
    }

    const size_t HB  = (size_t)SEQ * DIM;
    const size_t HBQ = (size_t)SEQ * QKN;

    // Combined input layernorms (keys->kn, values->vn), single launch.
    ln2_h<<<dim3(MROWS / 8, 2), 256>>>(keys, qk_g, qk_b, kn,
                                       values, vn_g, vn_b, vn);
    cudaEventRecord(eKN, 0);
    cudaStreamWaitEvent(sB, eKN, 0);

    // --- stream B: full v-GEMM, then batch-1 chain
    gemm_mma<true><<<dim3(DIM / 128, MROWS / 128), 256, GEMM_SMEM, sB>>>(
        vn, w_v, nullptr, vh, DIM, DIM, DIM);
    cudaEventRecord(eV, sB);
    gemm_mma<true><<<dim3(QKN / 128, SEQ / 128), 256, GEMM_SMEM, sB>>>(
        kn + HB, w_qk, nullptr, qkh + HBQ, DIM, QKN, QKN);
    lnqk2_h<<<dim3(SEQ / 8, 2), 256, 0, sB>>>(qkh + HBQ, query_g, query_b,
                                              key_g, key_b, qh + HB, kh + HB);
    flash_mma<<<dim3(SEQ / FQ_ROWS, HEADS), 256, FLASH_SMEM, sB>>>(
        qh + HB, kh + HB, vh + HB, ao + HB);
    gemm_mma<false><<<dim3(DIM / 128, SEQ / 128), 256, GEMM_SMEM, sB>>>(
        ao + HB, w_out, b_out, out + HB, DIM, DIM, DIM);
    cudaEventRecord(eB1, sB);

    // --- stream A: batch-0 chain
    gemm_mma<true><<<dim3(QKN / 128, SEQ / 128), 256, GEMM_SMEM>>>(
        kn, w_qk, nullptr, qkh, DIM, QKN, QKN);
    lnqk2_h<<<dim3(SEQ / 8, 2), 256>>>(qkh, query_g, query_b,
                                       key_g, key_b, qh, kh);
    cudaStreamWaitEvent(0, eV, 0);
    flash_mma<<<dim3(SEQ / FQ_ROWS, HEADS), 256, FLASH_SMEM>>>(qh, kh, vh, ao);
    gemm_mma<false><<<dim3(DIM / 128, SEQ / 128), 256, GEMM_SMEM>>>(
        ao, w_out, b_out, out, DIM, DIM, DIM);

    cudaStreamWaitEvent(0, eB1, 0);
}

// round 17
// speedup vs baseline: 1.0042x; 1.0042x over previous
#include <cuda_runtime.h>
#include <cuda_fp16.h>
#include <cstdint>

// ---------------------------------------------------------------------------
// B=2, N=2048, KD=VD=ID=1024, H=16, HD=64
// ---------------------------------------------------------------------------
#define MROWS 4096
#define DIM   1024
#define QKN   2048
#define HEADS 16
#define HDIM  64
#define SEQ   2048
// folded into q at lnqk: SCALE * log2(e) = 1.44269504 / 32
#define K2E 0.0450842200f

// ---------------------------------------------------------------------------
// Device scratch
// ---------------------------------------------------------------------------
__device__ __half g_kn[MROWS * DIM];
__device__ __half g_vn[MROWS * DIM];
__device__ __half g_qkh[MROWS * QKN];
__device__ __half g_qh[MROWS * DIM];
__device__ __half g_kh[MROWS * DIM];
__device__ __half g_vh[MROWS * DIM];
__device__ __half g_ao[MROWS * DIM];

// ---------------------------------------------------------------------------
// PTX helpers
// ---------------------------------------------------------------------------
__device__ __forceinline__ uint32_t smem_u32(const void* p) {
    return (uint32_t)__cvta_generic_to_shared(p);
}
#define CP16(dst, src) \
    asm volatile("cp.async.cg.shared.global [%0], [%1], 16;" :: "r"(dst), "l"(src))
#define CP_COMMIT() asm volatile("cp.async.commit_group;" ::: "memory")
#define CP_WAIT(n)  asm volatile("cp.async.wait_group %0;" :: "n"(n) : "memory")

__device__ __forceinline__ void ldm_x4(uint32_t* r, uint32_t a) {
    asm volatile("ldmatrix.sync.aligned.m8n8.x4.shared.b16 {%0,%1,%2,%3}, [%4];"
        : "=r"(r[0]), "=r"(r[1]), "=r"(r[2]), "=r"(r[3]) : "r"(a));
}
__device__ __forceinline__ void ldm_x4t(uint32_t* r, uint32_t a) {
    asm volatile("ldmatrix.sync.aligned.m8n8.x4.trans.shared.b16 {%0,%1,%2,%3}, [%4];"
        : "=r"(r[0]), "=r"(r[1]), "=r"(r[2]), "=r"(r[3]) : "r"(a));
}
__device__ __forceinline__ void mma16816(float* c, const uint32_t* a,
                                         uint32_t b0, uint32_t b1) {
    asm volatile(
        "mma.sync.aligned.m16n8k16.row.col.f32.f16.f16.f32 "
        "{%0,%1,%2,%3}, {%4,%5,%6,%7}, {%8,%9}, {%0,%1,%2,%3};"
        : "+f"(c[0]), "+f"(c[1]), "+f"(c[2]), "+f"(c[3])
        : "r"(a[0]), "r"(a[1]), "r"(a[2]), "r"(a[3]), "r"(b0), "r"(b1));
}
// fp16-accumulator variant: C is 2 packed half2 regs. (flash QK only)
__device__ __forceinline__ void mma16816h(uint32_t* c, const uint32_t* a,
                                          uint32_t b0, uint32_t b1) {
    asm volatile(
        "mma.sync.aligned.m16n8k16.row.col.f16.f16.f16.f16 "
        "{%0,%1}, {%2,%3,%4,%5}, {%6,%7}, {%0,%1};"
        : "+r"(c[0]), "+r"(c[1])
        : "r"(a[0]), "r"(a[1]), "r"(a[2]), "r"(a[3]), "r"(b0), "r"(b1));
}
__device__ __forceinline__ uint32_t pack_half2(float lo, float hi) {
    uint32_t u;
    asm("cvt.rn.f16x2.f32 %0, %1, %2;" : "=r"(u) : "f"(hi), "f"(lo));
    return u;
}
__device__ __forceinline__ __half2 u2h(uint32_t u) {
    return *reinterpret_cast<__half2*>(&u);
}
__device__ __forceinline__ uint32_t h2u(__half2 h) {
    return *reinterpret_cast<uint32_t*>(&h);
}

// Packed softmax numerator: 2^(s') * 2^-6, fully in half2.
__device__ __forceinline__ __half2 pexp2h(uint32_t sbits) {
    const __half2 s2 = u2h(sbits);
    const __half2 mg = u2h(0x66046604u);           // 1540.0 x2
    const __half2 t2 = __hadd2(s2, mg);            // round-to-int (RN)
    const __half2 f2 = __hsub2(t2, mg);            // k (integer)
    const __half2 r2 = __hsub2(s2, f2);            // frac in [-0.5, 0.5]
    __half2 p = __hfma2(u2h(0x20EC20ECu), r2, u2h(0x2B1A2B1Au));
    p = __hfma2(p, r2, u2h(0x33B033B0u));
    p = __hfma2(p, r2, u2h(0x398C398Cu));
    p = __hfma2(p, r2, u2h(0x3C003C00u));
    const uint32_t sc = ((h2u(t2) << 10) & 0x1C001C00u) + 0x14001400u;
    return __hmul2(p, u2h(sc));
}

// ---------------------------------------------------------------------------
// Combined input LayerNorm: blockIdx.y selects (keys->kn) or (values->vn).
// One warp per row, shfl-only reduce. fp32 in -> fp16 out.
// ---------------------------------------------------------------------------
__global__ __launch_bounds__(256) void ln2_h(
    const float* __restrict__ x0, const float* __restrict__ g0,
    const float* __restrict__ b0, __half* __restrict__ y0,
    const float* __restrict__ x1, const float* __restrict__ g1,
    const float* __restrict__ b1, __half* __restrict__ y1)
{
    const float* x = blockIdx.y ? x1 : x0;
    const float* g = blockIdx.y ? g1 : g0;
    const float* b = blockIdx.y ? b1 : b0;
    __half*      y = blockIdx.y ? y1 : y0;

    const int lane = threadIdx.x & 31;
    const size_t row = (size_t)blockIdx.x * 8 + (threadIdx.x >> 5);
    const float* xr = x + row * (size_t)DIM;

    float4 v[8], gv[8], bv[8];
    float s = 0.f, ss = 0.f;
    #pragma unroll
    for (int i = 0; i < 8; i++) {
        const int c4 = i * 32 + lane;
        v[i]  = *(const float4*)(xr + c4 * 4);
        gv[i] = *(const float4*)(g + c4 * 4);
        bv[i] = *(const float4*)(b + c4 * 4);
    }
    #pragma unroll
    for (int i = 0; i < 8; i++) {
        s  += v[i].x + v[i].y + v[i].z + v[i].w;
        ss += v[i].x*v[i].x + v[i].y*v[i].y + v[i].z*v[i].z + v[i].w*v[i].w;
    }
    #pragma unroll
    for (int m = 16; m; m >>= 1) {
        s  += __shfl_xor_sync(0xffffffffu, s,  m);
        ss += __shfl_xor_sync(0xffffffffu, ss, m);
    }
    const float mu   = s * (1.0f / 1024.0f);
    const float rstd = rsqrtf(ss * (1.0f / 1024.0f) - mu * mu + 1e-5f);

    #pragma unroll
    for (int i = 0; i < 8; i++) {
        const int c4 = i * 32 + lane;
        uint2 o;
        o.x = pack_half2((v[i].x - mu) * rstd * gv[i].x + bv[i].x,
                         (v[i].y - mu) * rstd * gv[i].y + bv[i].y);
        o.y = pack_half2((v[i].z - mu) * rstd * gv[i].z + bv[i].z,
                         (v[i].w - mu) * rstd * gv[i].w + bv[i].w);
        *(uint2*)(y + row * (size_t)DIM + c4 * 4) = o;
    }
}

// ---------------------------------------------------------------------------
// q/k LayerNorm, split: blockIdx.y = 0 -> q half (pre-scaled by K2E),
// 1 -> k half. One warp per row-half.
// ---------------------------------------------------------------------------
__global__ __launch_bounds__(256) void lnqk2_h(
    const __half* __restrict__ qk,
    const float* __restrict__ qg, const float* __restrict__ qb,
    const float* __restrict__ kg, const float* __restrict__ kb,
    __half* __restrict__ qh, __half* __restrict__ kh)
{
    const int isK = blockIdx.y;
    const float* g = isK ? kg : qg;
    const float* b = isK ? kb : qb;
    __half*      y = isK ? kh : qh;
    const float post = isK ? 1.0f : K2E;

    const int lane = threadIdx.x & 31;
    const size_t row = (size_t)blockIdx.x * 8 + (threadIdx.x >> 5);
    const __half* xr = qk + row * (size_t)QKN + isK * DIM;

    uint2 u[8];
    float4 gv[8], bv[8];
    float s = 0.f, ss = 0.f;
    #pragma unroll
    for (int i = 0; i < 8; i++) {
        const int c4 = i * 32 + lane;
        u[i]  = *(const uint2*)(xr + c4 * 4);
        gv[i] = *(const float4*)(g + c4 * 4);
        bv[i] = *(const float4*)(b + c4 * 4);
    }
    #pragma unroll
    for (int i = 0; i < 8; i++) {
        const __half2* h = (const __half2*)&u[i];
        #pragma unroll
        for (int p = 0; p < 2; p++) {
            const float2 f = __half22float2(h[p]);
            s += f.x + f.y;  ss += f.x*f.x + f.y*f.y;
        }
    }
    #pragma unroll
    for (int m = 16; m; m >>= 1) {
        s  += __shfl_xor_sync(0xffffffffu, s,  m);
        ss += __shfl_xor_sync(0xffffffffu, ss, m);
    }
    const float mu = s * (1.0f / 1024.0f);
    const float r  = rsqrtf(ss * (1.0f / 1024.0f) - mu * mu + 1e-5f);

    #pragma unroll
    for (int i = 0; i < 8; i++) {
        const int c4 = i * 32 + lane;
        const __half2* h = (const __half2*)&u[i];
        const float2 f0 = __half22float2(h[0]), f1 = __half22float2(h[1]);
        uint2 o;
        o.x = pack_half2(((f0.x - mu) * r * gv[i].x + bv[i].x) * post,
                         ((f0.y - mu) * r * gv[i].y + bv[i].y) * post);
        o.y = pack_half2(((f1.x - mu) * r * gv[i].z + bv[i].z) * post,
                         ((f1.y - mu) * r * gv[i].w + bv[i].w) * post);
        *(uint2*)(y + row * (size_t)DIM + c4 * 4) = o;
    }
}

// ---------------------------------------------------------------------------
// fp16 GEMM, direct-B (R11/R13/R15, unchanged):
// C[M,N] = A[M,K] @ B[K,N] (+bias).
// A: fp16 [M][K], cp.async 3-stage, ldmatrix. B: fp32 [K][N] raw weights,
// LDG+cvt+STS 2-stage, ldmatrix.trans fragments.
// CTA 128x128, 8 warps (2x4), warp tile 64x32, K-chunk 64, 2 CTAs/SM.
// ---------------------------------------------------------------------------
#define GST  72
#define BST  136
#define ASTG (128 * GST)
#define BSTG (64 * BST)
#define GEMM_SMEM ((3 * ASTG + 2 * BSTG) * 2)   // 90112 B

template <bool HALF_OUT>
__global__ __launch_bounds__(256, 2) void gemm_mma(
    const __half* __restrict__ A, const float* __restrict__ Bf,
    const float* __restrict__ bias, void* __restrict__ Cv,
    int K, int ldB, int ldC)
{
    extern __shared__ __align__(16) __half sm[];
    const uint32_t sb  = smem_u32(sm);
    const uint32_t bb0 = sb + 3 * ASTG * 2;

    const int tid  = threadIdx.x;
    const int wid  = tid >> 5, lane = tid & 31;
    const int g = lane >> 2, tg = lane & 3;
    const int m0 = (wid >> 2) * 64, n0 = (wid & 3) * 32;
    const int lr = (lane & 7) + ((lane >> 3) & 1) * 8;
    const int lc = (lane >> 4) * 8;

    const __half* Ag = A  + (size_t)(blockIdx.y * 128) * K;
    const float*  Bg = Bf + blockIdx.x * 128;

    const int lrow = tid >> 3, lcol = (tid & 7) * 8;   // A cp.async mapping
    const int brow = tid >> 5, bcol = (tid & 31) * 4;  // B LDG/STS mapping

    auto load_a = [&](int s, int kc) {
        const uint32_t ab = sb + s * ASTG * 2;
        #pragma unroll
        for (int i = 0; i < 4; i++) {
            const int row = lrow + i * 32;
            CP16(ab + (row * GST + lcol) * 2, Ag + (size_t)row * K + kc * 64 + lcol);
        }
        CP_COMMIT();
    };
    auto ldg_b = [&](float4* bv, int kc, int half) {
        const float* Bk = Bg + (size_t)(kc * 64) * ldB;
        #pragma unroll
        for (int i = 0; i < 4; i++) {
            const int row = brow + (half * 4 + i) * 8;
            bv[i] = *(const float4*)(Bk + (size_t)row * ldB + bcol);
        }
    };
    auto sts_b = [&](const float4* bv, uint32_t bbuf, int half) {
        #pragma unroll
        for (int i = 0; i < 4; i++) {
            const int row = brow + (half * 4 + i) * 8;
            const uint32_t u0 = pack_half2(bv[i].x, bv[i].y);
            const uint32_t u1 = pack_half2(bv[i].z, bv[i].w);
            asm volatile("st.shared.v2.b32 [%0], {%1,%2};"
                :: "r"(bbuf + (row * BST + bcol) * 2), "r"(u0), "r"(u1));
        }
    };

    float acc[4][4][4];
    #pragma unroll
    for (int i = 0; i < 4; i++)
        #pragma unroll
        for (int j = 0; j < 4; j++)
            #pragma unroll
            for (int q = 0; q < 4; q++) acc[i][j][q] = 0.f;

    const int nk = K >> 6;
    load_a(0, 0);
    load_a(1, 1);
    {   // B prologue: fill stage 0
        float4 bv[4];
        ldg_b(bv, 0, 0); sts_b(bv, bb0, 0);
        ldg_b(bv, 0, 1); sts_b(bv, bb0, 1);
    }

    for (int kc = 0; kc < nk; kc++) {
        if (kc + 1 < nk) CP_WAIT(1); else CP_WAIT(0);
        __syncthreads();
        if (kc + 2 < nk) load_a((kc + 2) % 3, kc + 2);

        const uint32_t ab   = sb + (kc % 3) * ASTG * 2;
        const uint32_t bbuf = bb0 + (kc & 1) * BSTG * 2;
        const uint32_t bnxt = bb0 + ((kc + 1) & 1) * BSTG * 2;
        const bool more = (kc + 1 < nk);

        float4 bv[4];
        if (more) ldg_b(bv, kc + 1, 0);

        #pragma unroll
        for (int ks = 0; ks < 4; ks++) {
            if (ks == 2 && more) {
                sts_b(bv, bnxt, 0);
                ldg_b(bv, kc + 1, 1);
            }
            uint32_t a[4][4];
            #pragma unroll
            for (int mi = 0; mi < 4; mi++)
                ldm_x4(a[mi], ab + ((m0 + mi * 16 + lr) * GST + ks * 16 + lc) * 2);
            #pragma unroll
            for (int np = 0; np < 2; np++) {
                uint32_t bf[4];
                ldm_x4t(bf, bbuf + ((ks * 16 + lr) * BST + n0 + np * 16 + lc) * 2);
                #pragma unroll
                for (int ni2 = 0; ni2 < 2; ni2++) {
                    #pragma unroll
                    for (int mi = 0; mi < 4; mi++)
                        mma16816(acc[mi][np * 2 + ni2], a[mi],
                                 bf[ni2 * 2], bf[ni2 * 2 + 1]);
                }
            }
        }
        if (more) sts_b(bv, bnxt, 1);
        __syncthreads();
    }

    const int crow = blockIdx.y * 128 + m0;
    const int ccol = blockIdx.x * 128 + n0;
    #pragma unroll
    for (int mi = 0; mi < 4; mi++) {
        #pragma unroll
        for (int ni = 0; ni < 4; ni++) {
            const int r = crow + mi * 16 + g;
            const int c = ccol + ni * 8 + 2 * tg;
            float2 v0 = make_float2(acc[mi][ni][0], acc[mi][ni][1]);
            float2 v1 = make_float2(acc[mi][ni][2], acc[mi][ni][3]);
            if (bias) {
                const float2 bb2 = *(const float2*)(bias + c);
                v0.x += bb2.x; v0.y += bb2.y; v1.x += bb2.x; v1.y += bb2.y;
            }
            if (HALF_OUT) {
                __half* C = (__half*)Cv;
                *(uint32_t*)&C[(size_t)r * ldC + c]       = pack_half2(v0.x, v0.y);
                *(uint32_t*)&C[(size_t)(r + 8) * ldC + c] = pack_half2(v1.x, v1.y);
            } else {
                float* C = (float*)Cv;
                *(float2*)&C[(size_t)r * ldC + c]       = v0;
                *(float2*)&C[(size_t)(r + 8) * ldC + c] = v1;
            }
        }
    }
}

// ---------------------------------------------------------------------------
// Flash attention (R10-R16, unchanged): fp16-accum QK, packed half2 softmax,
// fp32-accum PV. CTA = 128 q-rows, 8 warps x 16, 2 CTAs/SM.
// ---------------------------------------------------------------------------
#define FQ_ROWS 128
#define FKV_OFF (FQ_ROWS * GST)
#define FSTAGE  (128 * GST)
#define FLASH_SMEM ((FQ_ROWS * GST + 2 * FSTAGE) * 2)   // 55296 B

__global__ __launch_bounds__(256, 2) void flash_mma(
    const __half* __restrict__ Q, const __half* __restrict__ Kg,
    const __half* __restrict__ Vg, __half* __restrict__ Og)
{
    extern __shared__ __align__(16) __half sm[];
    const uint32_t sb = smem_u32(sm);

    const int tid  = threadIdx.x;
    const int warp = tid >> 5, lane = tid & 31;
    const int g = lane >> 2, tg = lane & 3;
    const int m0 = warp * 16;
    const int lr = (lane & 7) + ((lane >> 3) & 1) * 8;
    const int lc = (lane >> 4) * 8;

    const size_t q0 = (size_t)blockIdx.x * FQ_ROWS;
    const int hc = blockIdx.y * HDIM;

    const int lrow = tid >> 3, lcol = (tid & 7) * 8;

    {
        const __half* qg = Q + q0 * DIM + hc;
        #pragma unroll
        for (int i = 0; i < 4; i++) {
            const int row = lrow + i * 32;
            CP16(sb + (row * GST + lcol) * 2, qg + (size_t)row * DIM + lcol);
        }
    }
    auto load_kv = [&](int s, int kt) {
        const __half* kg = Kg + (size_t)(kt * 64) * DIM + hc;
        const __half* vg = Vg + (size_t)(kt * 64) * DIM + hc;
        const uint32_t kb = sb + (FKV_OFF + s * FSTAGE) * 2;
        const uint32_t vb = kb + 64 * GST * 2;
        #pragma unroll
        for (int i = 0; i < 2; i++) {
            const int row = lrow + i * 32;
            CP16(kb + (row * GST + lcol) * 2, kg + (size_t)row * DIM + lcol);
            CP16(vb + (row * GST + lcol) * 2, vg + (size_t)row * DIM + lcol);
        }
        CP_COMMIT();
    };
    load_kv(0, 0);

    uint32_t qf[4][4];
    float o[8][4];
    #pragma unroll
    for (int j = 0; j < 8; j++)
        #pragma unroll
        for (int q = 0; q < 4; q++) o[j][q] = 0.f;
    float l0 = 0.f, l1 = 0.f;

    for (int kt = 0; kt < SEQ / 64; kt++) {
        if (kt + 1 < SEQ / 64) { load_kv((kt + 1) & 1, kt + 1); CP_WAIT(1); }
        else                   { CP_WAIT(0); }
        __syncthreads();

        if (kt == 0) {
            #pragma unroll
            for (int s = 0; s < 4; s++)
                ldm_x4(qf[s], sb + ((m0 + lr) * GST + s * 16 + lc) * 2);
        }

        const uint32_t kb = sb + (FKV_OFF + (kt & 1) * FSTAGE) * 2;
        const uint32_t vb = kb + 64 * GST * 2;

        uint32_t sh[8][2];
        #pragma unroll
        for (int j = 0; j < 8; j++) { sh[j][0] = 0u; sh[j][1] = 0u; }
        #pragma unroll
        for (int ks = 0; ks < 4; ks++) {
            uint32_t bf[4][4];
            #pragma unroll
            for (int np = 0; np < 4; np++)
                ldm_x4(bf[np], kb + ((np * 16 + lr) * GST + ks * 16 + lc) * 2);
            #pragma unroll
            for (int j = 0; j < 8; j++)
                mma16816h(sh[j], qf[ks], bf[j >> 1][j & 1], bf[j >> 1][(j & 1) + 2]);
        }

        uint32_t pf[4][4];
        __half2 la = u2h(0u), lb = u2h(0u);
        #pragma unroll
        for (int j = 0; j < 8; j++) {
            const __half2 pa = pexp2h(sh[j][0]);
            const __half2 pb = pexp2h(sh[j][1]);
            la = __hadd2(la, pa);
            lb = __hadd2(lb, pb);
            pf[j >> 1][(j & 1) * 2]     = h2u(pa);
            pf[j >> 1][(j & 1) * 2 + 1] = h2u(pb);
        }
        l0 += __low2float(la) + __high2float(la);
        l1 += __low2float(lb) + __high2float(lb);

        #pragma unroll
        for (int ks = 0; ks < 4; ks++) {
            uint32_t vf[4][4];
            #pragma unroll
            for (int np = 0; np < 4; np++)
                ldm_x4t(vf[np], vb + ((ks * 16 + lr) * GST + np * 16 + lc) * 2);
            #pragma unroll
            for (int j = 0; j < 8; j++)
                mma16816(o[j], pf[ks],
                         vf[j >> 1][(j & 1) * 2], vf[j >> 1][(j & 1) * 2 + 1]);
        }
        __syncthreads();
    }

    l0 += __shfl_xor_sync(0xffffffffu, l0, 1);
    l0 += __shfl_xor_sync(0xffffffffu, l0, 2);
    l1 += __shfl_xor_sync(0xffffffffu, l1, 1);
    l1 += __shfl_xor_sync(0xffffffffu, l1, 2);
    const float inv0 = 1.0f / l0, inv1 = 1.0f / l1;

    const size_t row0 = q0 + m0 + g;
    #pragma unroll
    for (int j = 0; j < 8; j++) {
        const int c = hc + j * 8 + 2 * tg;
        *(uint32_t*)&Og[row0 * DIM + c]       = pack_half2(o[j][0] * inv0, o[j][1] * inv0);
        *(uint32_t*)&Og[(row0 + 8) * DIM + c] = pack_half2(o[j][2] * inv1, o[j][3] * inv1);
    }
}

// ---------------------------------------------------------------------------
// Launcher: R15 schedule with tail rebalance — out-proj of batch 1 migrated
// to stream A (gated on flash_b1), so both streams end with equal work.
// ---------------------------------------------------------------------------
extern "C" void kernel_launch(void* const* d_in, const int* in_sizes, int n_in,
                              void* d_out, int out_size)
{
    const float* keys    = (const float*)d_in[0];
    const float* values  = (const float*)d_in[1];
    const float* qk_g    = (const float*)d_in[2];
    const float* qk_b    = (const float*)d_in[3];
    const float* vn_g    = (const float*)d_in[4];
    const float* vn_b    = (const float*)d_in[5];
    const float* key_g   = (const float*)d_in[6];
    const float* key_b   = (const float*)d_in[7];
    const float* query_g = (const float*)d_in[8];
    const float* query_b = (const float*)d_in[9];
    const float* w_qk    = (const float*)d_in[10];
    const float* w_v     = (const float*)d_in[11];
    const float* w_out   = (const float*)d_in[12];
    const float* b_out   = (const float*)d_in[13];
    float* out = (float*)d_out;

    __half *kn, *vn, *qkh, *qh, *kh, *vh, *ao;
    cudaGetSymbolAddress((void**)&kn,  g_kn);
    cudaGetSymbolAddress((void**)&vn,  g_vn);
    cudaGetSymbolAddress((void**)&qkh, g_qkh);
    cudaGetSymbolAddress((void**)&qh,  g_qh);
    cudaGetSymbolAddress((void**)&kh,  g_kh);
    cudaGetSymbolAddress((void**)&vh,  g_vh);
    cudaGetSymbolAddress((void**)&ao,  g_ao);

    static cudaStream_t sB = nullptr;
    static cudaEvent_t  eKN = nullptr, eV = nullptr, eF1 = nullptr;
    if (!sB) {
        cudaStreamCreateWithFlags(&sB, cudaStreamNonBlocking);
        cudaEventCreateWithFlags(&eKN, cudaEventDisableTiming);
        cudaEventCreateWithFlags(&eV,  cudaEventDisableTiming);
        cudaEventCreateWithFlags(&eF1, cudaEventDisableTiming);
        cudaFuncSetAttribute(gemm_mma<false>,
            cudaFuncAttributeMaxDynamicSharedMemorySize, GEMM_SMEM);
        cudaFuncSetAttribute(gemm_mma<true>,
            cudaFuncAttributeMaxDynamicSharedMemorySize, GEMM_SMEM);
        cudaFuncSetAttribute(flash_mma,
            cudaFuncAttributeMaxDynamicSharedMemorySize, FLASH_SMEM);
    }

    const size_t HB  = (size_t)SEQ * DIM;
    const size_t HBQ = (size_t)SEQ * QKN;

    // Combined input layernorms (keys->kn, values->vn), single launch.
    ln2_h<<<dim3(MROWS / 8, 2), 256>>>(keys, qk_g, qk_b, kn,
                                       values, vn_g, vn_b, vn);
    cudaEventRecord(eKN, 0);
    cudaStreamWaitEvent(sB, eKN, 0);

    // --- stream B: full v-GEMM, then batch-1 chain up to flash
    gemm_mma<true><<<dim3(DIM / 128, MROWS / 128), 256, GEMM_SMEM, sB>>>(
        vn, w_v, nullptr, vh, DIM, DIM, DIM);
    cudaEventRecord(eV, sB);
    gemm_mma<true><<<dim3(QKN / 128, SEQ / 128), 256, GEMM_SMEM, sB>>>(
        kn + HB, w_qk, nullptr, qkh + HBQ, DIM, QKN, QKN);
    lnqk2_h<<<dim3(SEQ / 8, 2), 256, 0, sB>>>(qkh + HBQ, query_g, query_b,
                                              key_g, key_b, qh + HB, kh + HB);
    flash_mma<<<dim3(SEQ / FQ_ROWS, HEADS), 256, FLASH_SMEM, sB>>>(
        qh + HB, kh + HB, vh + HB, ao + HB);
    cudaEventRecord(eF1, sB);

    // --- stream A: batch-0 chain, then batch-1 out-proj (tail rebalance)
    gemm_mma<true><<<dim3(QKN / 128, SEQ / 128), 256, GEMM_SMEM>>>(
        kn, w_qk, nullptr, qkh, DIM, QKN, QKN);
    lnqk2_h<<<dim3(SEQ / 8, 2), 256>>>(qkh, query_g, query_b,
                                       key_g, key_b, qh, kh);
    cudaStreamWaitEvent(0, eV, 0);
    flash_mma<<<dim3(SEQ / FQ_ROWS, HEADS), 256, FLASH_SMEM>>>(qh, kh, vh, ao);
    gemm_mma<false><<<dim3(DIM / 128, SEQ / 128), 256, GEMM_SMEM>>>(
        ao, w_out, b_out, out, DIM, DIM, DIM);
    cudaStreamWaitEvent(0, eF1, 0);
    gemm_mma<false><<<dim3(DIM / 128, SEQ / 128), 256, GEMM_SMEM>>>(
        ao + HB, w_out, b_out, out + HB, DIM, DIM, DIM);
}